// round 4
// baseline (speedup 1.0000x reference)
#include <cuda_runtime.h>
#include <cuda_bf16.h>

// Shapes (known): N=100000, E=3200000, F_IN=128, H=16, C=2
#define MAXN 100000
#define MAXE 3200000
#define SCAN_B 1024

// Static scratch (allocation-free per harness rules)
__device__ int    d_cnt[MAXN];       // in-degree (excl self loop)
__device__ int    d_off[MAXN];       // CSR row offsets (by dst)
__device__ int    d_cur[MAXN];       // fill cursors
__device__ int    d_srclist[MAXE];   // CSR column indices (src per dst-bucket)
__device__ int    d_bsum[256];       // scan block sums
__device__ float  d_dinv[MAXN];
__device__ float4 d_g1[MAXN * 4];    // g1[i] = (x@W1)[i]*dinv[i], 16 f32/node
__device__ float2 d_g2[MAXN];        // g2[i] = (h1@W2)[i]*dinv[i]

// ---------------------------------------------------------------------------
__global__ void k_zero(int N) {
    int i = blockIdx.x * blockDim.x + threadIdx.x;
    if (i < N) d_cnt[i] = 0;
}

__global__ void k_count(const int* __restrict__ dst, int E) {
    int e = blockIdx.x * blockDim.x + threadIdx.x;
    if (e < E) atomicAdd(&d_cnt[dst[e]], 1);
}

// Block-local exclusive scan (Hillis-Steele, inclusive then subtract self).
// Also computes dinv = rsqrt(deg+1) on the way.
__global__ void k_scan1(int N) {
    __shared__ int s[SCAN_B];
    int i = blockIdx.x * SCAN_B + threadIdx.x;
    int v = (i < N) ? d_cnt[i] : 0;
    s[threadIdx.x] = v;
    __syncthreads();
#pragma unroll
    for (int d = 1; d < SCAN_B; d <<= 1) {
        int t = (threadIdx.x >= d) ? s[threadIdx.x - d] : 0;
        __syncthreads();
        s[threadIdx.x] += t;
        __syncthreads();
    }
    if (i < N) {
        d_off[i]  = s[threadIdx.x] - v;      // block-local exclusive
        d_dinv[i] = rsqrtf((float)(v + 1));  // self loop adds 1
    }
    if (threadIdx.x == SCAN_B - 1) d_bsum[blockIdx.x] = s[SCAN_B - 1];
}

__global__ void k_scan2(int nb) {
    if (threadIdx.x == 0 && blockIdx.x == 0) {
        int run = 0;
        for (int b = 0; b < nb; b++) { int v = d_bsum[b]; d_bsum[b] = run; run += v; }
    }
}

__global__ void k_scan3(int N) {
    int i = blockIdx.x * SCAN_B + threadIdx.x;
    if (i < N) {
        int o = d_off[i] + d_bsum[blockIdx.x];
        d_off[i] = o;
        d_cur[i] = o;
    }
}

__global__ void k_fill(const int* __restrict__ src,
                       const int* __restrict__ dst, int E) {
    int e = blockIdx.x * blockDim.x + threadIdx.x;
    if (e >= E) return;
    int p = atomicAdd(&d_cur[dst[e]], 1);
    d_srclist[p] = src[e];
}

// ---------------------------------------------------------------------------
// GEMM1: 4 threads per node; thread p handles k in [32p, 32p+32), all 16 j.
// Butterfly-reduce the 16 partials across the 4 lanes, write g1 (scaled by dinv).
__global__ void k_gemm1(const float* __restrict__ x,
                        const float* __restrict__ W1, int N) {
    __shared__ float4 W1s[128 * 4];  // W1[k][j] as float4 over j
    for (int i = threadIdx.x; i < 512; i += blockDim.x)
        W1s[i] = ((const float4*)W1)[i];
    __syncthreads();

    int t = blockIdx.x * blockDim.x + threadIdx.x;
    int node = t >> 2;
    if (node >= N) return;
    int part = t & 3;

    float acc[16];
#pragma unroll
    for (int j = 0; j < 16; j++) acc[j] = 0.0f;

    const float4* x4 = (const float4*)x + (size_t)node * 32 + part * 8;
#pragma unroll
    for (int k4 = 0; k4 < 8; k4++) {
        float4 xv = __ldg(&x4[k4]);
        int kb = part * 32 + k4 * 4;
#pragma unroll
        for (int kk = 0; kk < 4; kk++) {
            float xs = (kk == 0) ? xv.x : (kk == 1) ? xv.y : (kk == 2) ? xv.z : xv.w;
#pragma unroll
            for (int j4 = 0; j4 < 4; j4++) {
                float4 w = W1s[(kb + kk) * 4 + j4];
                acc[j4 * 4 + 0] += xs * w.x;
                acc[j4 * 4 + 1] += xs * w.y;
                acc[j4 * 4 + 2] += xs * w.z;
                acc[j4 * 4 + 3] += xs * w.w;
            }
        }
    }
    // reduce across the 4 lanes of this node
#pragma unroll
    for (int j = 0; j < 16; j++) {
        acc[j] += __shfl_xor_sync(0xffffffffu, acc[j], 1);
        acc[j] += __shfl_xor_sync(0xffffffffu, acc[j], 2);
    }
    float dv = d_dinv[node];
    float4 g = make_float4(acc[part * 4 + 0] * dv, acc[part * 4 + 1] * dv,
                           acc[part * 4 + 2] * dv, acc[part * 4 + 3] * dv);
    d_g1[node * 4 + part] = g;
}

// ---------------------------------------------------------------------------
// Gather layer 1 (no atomics) + fused layer-2 GEMM.
// 4 threads per node; thread p accumulates float4 part p of sum_{src->i} g1[src],
// adds the self loop g1[i], then h=relu(dinv*acc+b1), partial (o0,o1) over its
// 4 hidden channels, butterfly-reduce, lane 0 writes g2[i].
__global__ void k_gather1(const float* __restrict__ b1,
                          const float* __restrict__ W2, int N) {
    int t = blockIdx.x * blockDim.x + threadIdx.x;
    int node = t >> 2;
    if (node >= N) return;
    int part = t & 3;

    int off = d_off[node];
    int deg = d_cnt[node];
    float4 a = d_g1[node * 4 + part];  // self loop

    int k = 0;
    for (; k + 1 < deg; k += 2) {
        int s0 = d_srclist[off + k];
        int s1 = d_srclist[off + k + 1];
        float4 g0 = d_g1[s0 * 4 + part];
        float4 g1 = d_g1[s1 * 4 + part];
        a.x += g0.x + g1.x;
        a.y += g0.y + g1.y;
        a.z += g0.z + g1.z;
        a.w += g0.w + g1.w;
    }
    if (k < deg) {
        int s0 = d_srclist[off + k];
        float4 g0 = d_g1[s0 * 4 + part];
        a.x += g0.x; a.y += g0.y; a.z += g0.z; a.w += g0.w;
    }

    float dv = d_dinv[node];
    float4 bb = __ldg(&((const float4*)b1)[part]);
    float h0 = fmaxf(a.x * dv + bb.x, 0.0f);
    float h1 = fmaxf(a.y * dv + bb.y, 0.0f);
    float h2 = fmaxf(a.z * dv + bb.z, 0.0f);
    float h3 = fmaxf(a.w * dv + bb.w, 0.0f);

    int jb = part * 4;
    float o0 = h0 * __ldg(&W2[(jb + 0) * 2 + 0]) + h1 * __ldg(&W2[(jb + 1) * 2 + 0])
             + h2 * __ldg(&W2[(jb + 2) * 2 + 0]) + h3 * __ldg(&W2[(jb + 3) * 2 + 0]);
    float o1 = h0 * __ldg(&W2[(jb + 0) * 2 + 1]) + h1 * __ldg(&W2[(jb + 1) * 2 + 1])
             + h2 * __ldg(&W2[(jb + 2) * 2 + 1]) + h3 * __ldg(&W2[(jb + 3) * 2 + 1]);

    o0 += __shfl_xor_sync(0xffffffffu, o0, 1);
    o0 += __shfl_xor_sync(0xffffffffu, o0, 2);
    o1 += __shfl_xor_sync(0xffffffffu, o1, 1);
    o1 += __shfl_xor_sync(0xffffffffu, o1, 2);

    if (part == 0) d_g2[node] = make_float2(o0 * dv, o1 * dv);
}

// Gather layer 2 + final bias: out[i] = dinv[i]*(sum g2[src] + g2[i]) + b2
__global__ void k_out(const float* __restrict__ b2, float2* __restrict__ out,
                      int N) {
    int i = blockIdx.x * blockDim.x + threadIdx.x;
    if (i >= N) return;
    int off = d_off[i];
    int deg = d_cnt[i];
    float2 a = d_g2[i];  // self loop
    int k = 0;
    for (; k + 1 < deg; k += 2) {
        int s0 = d_srclist[off + k];
        int s1 = d_srclist[off + k + 1];
        float2 g0 = d_g2[s0];
        float2 g1 = d_g2[s1];
        a.x += g0.x + g1.x;
        a.y += g0.y + g1.y;
    }
    if (k < deg) {
        float2 g0 = d_g2[d_srclist[off + k]];
        a.x += g0.x; a.y += g0.y;
    }
    float dv = d_dinv[i];
    out[i] = make_float2(a.x * dv + __ldg(&b2[0]), a.y * dv + __ldg(&b2[1]));
}

// ---------------------------------------------------------------------------
extern "C" void kernel_launch(void* const* d_in, const int* in_sizes, int n_in,
                              void* d_out, int out_size) {
    const float* x  = (const float*)d_in[0];
    const int*   ei = (const int*)d_in[1];   // int32 [2, E]
    const float* W1 = (const float*)d_in[2];
    const float* b1 = (const float*)d_in[3];
    const float* W2 = (const float*)d_in[4];
    const float* b2 = (const float*)d_in[5];

    int N = in_sizes[0] / 128;
    int E = in_sizes[1] / 2;
    const int* src = ei;
    const int* dst = ei + E;
    int nb = (N + SCAN_B - 1) / SCAN_B;

    k_zero<<<(N + 255) / 256, 256>>>(N);
    k_count<<<(E + 255) / 256, 256>>>(dst, E);
    k_scan1<<<nb, SCAN_B>>>(N);
    k_scan2<<<1, 32>>>(nb);
    k_scan3<<<nb, SCAN_B>>>(N);
    k_fill<<<(E + 255) / 256, 256>>>(src, dst, E);
    k_gemm1<<<(4 * N + 255) / 256, 256>>>(x, W1, N);
    k_gather1<<<(4 * N + 255) / 256, 256>>>(b1, W2, N);
    k_out<<<(N + 255) / 256, 256>>>(b2, (float2*)d_out, N);
}